// round 4
// baseline (speedup 1.0000x reference)
#include <cuda_runtime.h>
#include <math.h>
#include <stdint.h>

#define NN 100000
#define EE 640000
#define BB 2000
#define ND 256
#define ED 128
#define EMBD 256
#define LBLK 3

// ------------------------- scratch (no allocations allowed) -------------------------
__device__ float g_hn0[NN * ND];
__device__ float g_hn1[NN * ND];
__device__ float g_he0[EE * ED];
__device__ float g_he1[EE * ED];
__device__ float g_agg[NN * ND];
__device__ float g_dist[EE];
__device__ int   g_src[EE];
__device__ int   g_dst[EE];
__device__ int   g_bn[NN];
__device__ int   g_be[EE];
__device__ int   g_is64;
__device__ float g_sum_n[BB * ND];
__device__ float g_sum_e[BB * ED];
__device__ float g_cnt_n[BB];
__device__ float g_cnt_e[BB];
__device__ float g_hsub[BB * (ND + ED)];
__device__ float g_h1[BB * 2 * EMBD];

// ------------------------- dtype detection (int32 vs int64 indices) -------------------------
__global__ void k_detect(const unsigned int* __restrict__ u) {
    if (threadIdx.x != 0 || blockIdx.x != 0) return;
    int odd_nonzero = 0;
    for (int i = 0; i < 64; i++)
        if (u[2 * i + 1] != 0u) odd_nonzero++;
    g_is64 = (odd_nonzero == 0) ? 1 : 0;
}

__global__ void k_cvt_off(const void* __restrict__ p, int n, int off,
                          int* __restrict__ outp) {
    int i = blockIdx.x * 256 + threadIdx.x;
    if (i >= n) return;
    if (g_is64) outp[i] = (int)((const long long*)p)[off + i];
    else        outp[i] = ((const int*)p)[off + i];
}

// ------------------------- prep: edge distance -------------------------
__global__ void k_prep_edge(const float* __restrict__ pos) {
    int e = blockIdx.x * 256 + threadIdx.x;
    if (e >= EE) return;
    int s = g_src[e];
    int d = g_dst[e];
    float dx = pos[d * 3 + 0] - pos[s * 3 + 0];
    float dy = pos[d * 3 + 1] - pos[s * 3 + 1];
    float dz = pos[d * 3 + 2] - pos[s * 3 + 2];
    g_dist[e] = sqrtf(dx * dx + dy * dy + dz * dz);
}

// ------------------------- node/edge type embedding -------------------------
__global__ void k_embed_node(const float* __restrict__ hfeat,
                             const float* __restrict__ W,
                             float* __restrict__ outp) {
    __shared__ float sw[16 * 256];
    for (int i = threadIdx.x; i < 16 * 256; i += 256) sw[i] = W[i];
    __syncthreads();
    int c = threadIdx.x;
    int n0 = blockIdx.x * 8;
    for (int r = 0; r < 8; r++) {
        int n = n0 + r;
        if (n >= NN) return;
        float acc = 0.f;
#pragma unroll
        for (int k = 0; k < 16; k++) acc += hfeat[n * 16 + k] * sw[k * 256 + c];
        outp[n * 256 + c] = acc;
    }
}

__global__ void k_embed_edge(const float* __restrict__ hfeat,
                             const float* __restrict__ W,
                             float* __restrict__ outp) {
    __shared__ float sw[5 * 128];
    for (int i = threadIdx.x; i < 5 * 128; i += 256) sw[i] = W[i];
    __syncthreads();
    int sub = threadIdx.x >> 7;
    int c   = threadIdx.x & 127;
    int e0  = blockIdx.x * 16 + sub;
    for (int r = 0; r < 16; r += 2) {
        int e = e0 + r;
        if (e >= EE) return;
        float acc = 0.f;
#pragma unroll
        for (int k = 0; k < 5; k++) acc += hfeat[e * 5 + k] * sw[k * 128 + c];
        outp[e * 128 + c] = acc;
    }
}

// ------------------------- zero -------------------------
__global__ void k_zero(float* __restrict__ p, int n) {
    int i = blockIdx.x * blockDim.x + threadIdx.x;
    int str = gridDim.x * blockDim.x;
    for (; i < n; i += str) p[i] = 0.f;
}

// ------------------------- tf32 helpers -------------------------
__device__ __forceinline__ void split_tf32(float v, uint32_t& hi, uint32_t& lo) {
    asm("cvt.rna.tf32.f32 %0, %1;" : "=r"(hi) : "f"(v));
    float rem = v - __uint_as_float(hi);
    asm("cvt.rna.tf32.f32 %0, %1;" : "=r"(lo) : "f"(rem));
}

#define MMA_TF32(d, a0, a1, a2, a3, b0, b1)                                   \
    asm volatile("mma.sync.aligned.m16n8k8.row.col.f32.tf32.tf32.f32 "        \
                 "{%0,%1,%2,%3}, {%4,%5,%6,%7}, {%8,%9}, {%0,%1,%2,%3};"      \
                 : "+f"(d[0]), "+f"(d[1]), "+f"(d[2]), "+f"(d[3])             \
                 : "r"(a0), "r"(a1), "r"(a2), "r"(a3), "r"(b0), "r"(b1))

// ------------------------- tf32x3 tiled GEMM with fused gather -------------------------
// MODE 0 (edge update): A[e]=[he(128)|hn[src](256)|hn[dst](256)|dist(1)], K=641, N=128 -> relu
// MODE 1 (message):     A[e]=[hn[src](256)|he(128)], K=384, N=256 -> atomicAdd relu into agg[dst]
// MODE 2 (node update): A[n]=[hn(256)|agg(256)], K=512, N=256 -> hn + relu
// MODE 3 (final mlp1):  A=hsub[B,384], K=384, N=512 -> relu
// MODE 4 (final mlp2):  A=h1[B,512],  K=512, N=256 -> linear
template <int MODE>
__global__ __launch_bounds__(256, 1) void gemm_k(
    const float* __restrict__ P0, const float* __restrict__ P1,
    const float* __restrict__ Wb, const float* __restrict__ bias,
    float* __restrict__ Cout, const float* __restrict__ Extra,
    const int* __restrict__ src, const int* __restrict__ dst,
    const float* __restrict__ distv,
    int Mrows, int Kdim, int Ncols)
{
    __shared__ __align__(16) float As[16][136];
    __shared__ __align__(16) float Bs[16][136];
    const int tid = threadIdx.x;
    const int lane = tid & 31, w = tid >> 5;
    const int g = lane >> 2, t = lane & 3;
    const int wm = w & 1, wn = w >> 1;      // 2 x 4 warp grid, warp = 64m x 32n
    const int m0 = blockIdx.x * 128;
    const int n0 = blockIdx.y * 128;

    float acc[4][4][4];                     // [mt][nt][creg]
#pragma unroll
    for (int i = 0; i < 4; i++)
#pragma unroll
        for (int j = 0; j < 4; j++)
#pragma unroll
            for (int r = 0; r < 4; r++) acc[i][j][r] = 0.f;

    // A loader role: 128 rows x 16 k per panel, 2 half-k groups of 128 threads
    const int ar  = tid & 127;
    const int ak0 = (tid >> 7) * 8;
    const int rowg = m0 + ar;
    const bool rvalid = (rowg < Mrows);
    int rs = 0, rd = 0;
    if (MODE == 0) { if (rvalid) { rs = src[rowg]; rd = dst[rowg]; } }
    if (MODE == 1) { if (rvalid) { rs = src[rowg]; } }

    const int KT = (Kdim + 15) >> 4;
    for (int kt = 0; kt < KT; kt++) {
        // ---- load A panel (gathered, raw fp32) ----
#pragma unroll
        for (int j = 0; j < 8; j++) {
            int k = kt * 16 + ak0 + j;
            float v = 0.f;
            if (rvalid && k < Kdim) {
                if (MODE == 0) {
                    if (k < ED)               v = P0[rowg * ED + k];
                    else if (k < ED + ND)     v = P1[rs * ND + (k - ED)];
                    else if (k < ED + 2 * ND) v = P1[rd * ND + (k - ED - ND)];
                    else                      v = distv[rowg];
                } else if (MODE == 1) {
                    if (k < ND) v = P0[rs * ND + k];
                    else        v = P1[rowg * ED + (k - ND)];
                } else if (MODE == 2) {
                    if (k < ND) v = P0[rowg * ND + k];
                    else        v = P1[rowg * ND + (k - ND)];
                } else if (MODE == 3) {
                    v = P0[rowg * 384 + k];
                } else {
                    v = P0[rowg * 512 + k];
                }
            }
            As[ak0 + j][ar] = v;
        }
        // ---- load B panel (weights [K,N] row-major, coalesced float4) ----
#pragma unroll
        for (int r = 0; r < 2; r++) {
            int f  = tid + r * 256;
            int bk = f >> 5;
            int bc = (f & 31) * 4;
            int kg = kt * 16 + bk;
            float4 v = make_float4(0.f, 0.f, 0.f, 0.f);
            if (kg < Kdim) v = *(const float4*)(Wb + (size_t)kg * Ncols + n0 + bc);
            *(float4*)&Bs[bk][bc] = v;
        }
        __syncthreads();

#pragma unroll
        for (int kc = 0; kc < 2; kc++) {
            const int kb = kc * 8;
            // fragment loads + tf32 hi/lo split
            uint32_t ah[4][4], al[4][4];
#pragma unroll
            for (int mt = 0; mt < 4; mt++) {
                int mr = wm * 64 + mt * 16;
                float r0 = As[kb + t][mr + g];
                float r1 = As[kb + t][mr + g + 8];
                float r2 = As[kb + t + 4][mr + g];
                float r3 = As[kb + t + 4][mr + g + 8];
                split_tf32(r0, ah[mt][0], al[mt][0]);
                split_tf32(r1, ah[mt][1], al[mt][1]);
                split_tf32(r2, ah[mt][2], al[mt][2]);
                split_tf32(r3, ah[mt][3], al[mt][3]);
            }
            uint32_t bh[4][2], bl[4][2];
#pragma unroll
            for (int nt = 0; nt < 4; nt++) {
                int nc = wn * 32 + nt * 8 + g;
                float s0 = Bs[kb + t][nc];
                float s1 = Bs[kb + t + 4][nc];
                split_tf32(s0, bh[nt][0], bl[nt][0]);
                split_tf32(s1, bh[nt][1], bl[nt][1]);
            }
#pragma unroll
            for (int mt = 0; mt < 4; mt++)
#pragma unroll
                for (int nt = 0; nt < 4; nt++) {
                    MMA_TF32(acc[mt][nt], ah[mt][0], ah[mt][1], ah[mt][2], ah[mt][3],
                             bh[nt][0], bh[nt][1]);
                    MMA_TF32(acc[mt][nt], al[mt][0], al[mt][1], al[mt][2], al[mt][3],
                             bh[nt][0], bh[nt][1]);
                    MMA_TF32(acc[mt][nt], ah[mt][0], ah[mt][1], ah[mt][2], ah[mt][3],
                             bl[nt][0], bl[nt][1]);
                }
        }
        __syncthreads();
    }

    // ---- epilogue ----
#pragma unroll
    for (int mt = 0; mt < 4; mt++) {
#pragma unroll
        for (int half = 0; half < 2; half++) {
            int rg = m0 + wm * 64 + mt * 16 + g + half * 8;
            if (rg >= Mrows) continue;
            int dsti = 0;
            if (MODE == 1) dsti = dst[rg];
#pragma unroll
            for (int nt = 0; nt < 4; nt++) {
#pragma unroll
                for (int j = 0; j < 2; j++) {
                    int cg = n0 + wn * 32 + nt * 8 + 2 * t + j;
                    float v = acc[mt][nt][half * 2 + j] + bias[cg];
                    if (MODE == 0)      Cout[(size_t)rg * ED + cg] = fmaxf(v, 0.f);
                    else if (MODE == 1) atomicAdd(&Cout[(size_t)dsti * ND + cg], fmaxf(v, 0.f));
                    else if (MODE == 2) Cout[(size_t)rg * ND + cg] =
                                            Extra[(size_t)rg * ND + cg] + fmaxf(v, 0.f);
                    else if (MODE == 3) Cout[(size_t)rg * 512 + cg] = fmaxf(v, 0.f);
                    else                Cout[(size_t)rg * EMBD + cg] = v;
                }
            }
        }
    }
}

// ------------------------- pooling -------------------------
__global__ void k_count(const int* __restrict__ b, int n, float* __restrict__ cnt) {
    int i = blockIdx.x * 256 + threadIdx.x;
    if (i < n) atomicAdd(&cnt[b[i]], 1.f);
}

__global__ void k_pool_node(const float* __restrict__ hn) {
    int n0 = blockIdx.x * 128;
    int c = threadIdx.x;
    float acc = 0.f;
    int cur = -1;
    for (int i = 0; i < 128; i++) {
        int n = n0 + i;
        if (n >= NN) break;
        int b = g_bn[n];
        if (b != cur) {
            if (cur >= 0) atomicAdd(&g_sum_n[cur * ND + c], acc);
            cur = b; acc = 0.f;
        }
        acc += hn[(size_t)n * ND + c];
    }
    if (cur >= 0) atomicAdd(&g_sum_n[cur * ND + c], acc);
}

__global__ void k_pool_edge(const float* __restrict__ he) {
    int e0 = blockIdx.x * 512;
    int c = threadIdx.x;
    float acc = 0.f;
    int cur = -1;
    for (int i = 0; i < 512; i++) {
        int e = e0 + i;
        if (e >= EE) break;
        int b = g_be[e];
        if (b != cur) {
            if (cur >= 0) atomicAdd(&g_sum_e[cur * ED + c], acc);
            cur = b; acc = 0.f;
        }
        acc += he[(size_t)e * ED + c];
    }
    if (cur >= 0) atomicAdd(&g_sum_e[cur * ED + c], acc);
}

__global__ void k_hsub() {
    int idx = blockIdx.x * 256 + threadIdx.x;
    if (idx >= BB * (ND + ED)) return;
    int b = idx / (ND + ED);
    int c = idx % (ND + ED);
    float v;
    if (c < ND) v = g_sum_n[b * ND + c] / fmaxf(g_cnt_n[b], 1.f);
    else        v = g_sum_e[b * ED + (c - ND)] / fmaxf(g_cnt_e[b], 1.f);
    g_hsub[idx] = v;
}

__global__ void k_copy_batch(float* __restrict__ outp) {
    int i = blockIdx.x * 256 + threadIdx.x;
    if (i < NN) outp[i] = (float)g_bn[i];
}

// ------------------------- launch -------------------------
extern "C" void kernel_launch(void* const* d_in, const int* in_sizes, int n_in,
                              void* d_out, int out_size) {
    const float* h_node = (const float*)d_in[0];
    const float* pos    = (const float*)d_in[1];
    const float* h_edge = (const float*)d_in[2];
    const float* W_node = (const float*)d_in[3];
    const float* W_edge = (const float*)d_in[4];
    const float* W_eu   = (const float*)d_in[5];
    const float* b_eu   = (const float*)d_in[6];
    const float* W_msg  = (const float*)d_in[7];
    const float* b_msg  = (const float*)d_in[8];
    const float* W_nu   = (const float*)d_in[9];
    const float* b_nu   = (const float*)d_in[10];
    const float* Wf1    = (const float*)d_in[11];
    const float* bf1    = (const float*)d_in[12];
    const float* Wf2    = (const float*)d_in[13];
    const float* bf2    = (const float*)d_in[14];
    const void*  ei     = d_in[15];
    const void*  bn     = d_in[16];
    const void*  be     = d_in[17];
    float* outp = (float*)d_out;

    float *hn0, *hn1, *he0, *he1, *agg, *distp, *sumn, *sume, *cntn, *cnte, *hsub, *h1;
    int *srcp, *dstp, *bnp, *bep;
    cudaGetSymbolAddress((void**)&hn0, g_hn0);
    cudaGetSymbolAddress((void**)&hn1, g_hn1);
    cudaGetSymbolAddress((void**)&he0, g_he0);
    cudaGetSymbolAddress((void**)&he1, g_he1);
    cudaGetSymbolAddress((void**)&agg, g_agg);
    cudaGetSymbolAddress((void**)&distp, g_dist);
    cudaGetSymbolAddress((void**)&srcp, g_src);
    cudaGetSymbolAddress((void**)&dstp, g_dst);
    cudaGetSymbolAddress((void**)&bnp, g_bn);
    cudaGetSymbolAddress((void**)&bep, g_be);
    cudaGetSymbolAddress((void**)&sumn, g_sum_n);
    cudaGetSymbolAddress((void**)&sume, g_sum_e);
    cudaGetSymbolAddress((void**)&cntn, g_cnt_n);
    cudaGetSymbolAddress((void**)&cnte, g_cnt_e);
    cudaGetSymbolAddress((void**)&hsub, g_hsub);
    cudaGetSymbolAddress((void**)&h1, g_h1);

    // normalize index dtypes
    k_detect<<<1, 32>>>((const unsigned int*)ei);
    k_cvt_off<<<(EE + 255) / 256, 256>>>(ei, EE, 0,  srcp);
    k_cvt_off<<<(EE + 255) / 256, 256>>>(ei, EE, EE, dstp);
    k_cvt_off<<<(NN + 255) / 256, 256>>>(bn, NN, 0,  bnp);
    k_cvt_off<<<(EE + 255) / 256, 256>>>(be, EE, 0,  bep);

    k_prep_edge<<<(EE + 255) / 256, 256>>>(pos);
    k_embed_node<<<NN / 8, 256>>>(h_node, W_node, hn0);
    k_embed_edge<<<EE / 16, 256>>>(h_edge, W_edge, he0);

    float *hnc = hn0, *hnn = hn1, *hec = he0, *hen = he1;
    for (int l = 0; l < LBLK; l++) {
        gemm_k<0><<<dim3(EE / 128, 1), 256>>>(hec, hnc,
            W_eu + (size_t)l * 641 * 128, b_eu + l * 128,
            hen, nullptr, srcp, dstp, distp, EE, 641, 128);
        k_zero<<<4096, 256>>>(agg, NN * ND);
        gemm_k<1><<<dim3(EE / 128, 2), 256>>>(hnc, hen,
            W_msg + (size_t)l * 384 * 256, b_msg + l * 256,
            agg, nullptr, srcp, dstp, nullptr, EE, 384, 256);
        gemm_k<2><<<dim3((NN + 127) / 128, 2), 256>>>(hnc, agg,
            W_nu + (size_t)l * 512 * 256, b_nu + l * 256,
            hnn, hnc, nullptr, nullptr, nullptr, NN, 512, 256);
        { float* tp = hnc; hnc = hnn; hnn = tp; }
        { float* tp = hec; hec = hen; hen = tp; }
    }

    // pooling
    k_zero<<<256, 256>>>(sumn, BB * ND);
    k_zero<<<256, 256>>>(sume, BB * ED);
    k_zero<<<8, 256>>>(cntn, BB);
    k_zero<<<8, 256>>>(cnte, BB);
    k_count<<<(NN + 255) / 256, 256>>>(bnp, NN, cntn);
    k_count<<<(EE + 255) / 256, 256>>>(bep, EE, cnte);
    k_pool_node<<<(NN + 127) / 128, 256>>>(hnc);
    k_pool_edge<<<(EE + 511) / 512, 128>>>(hec);
    k_hsub<<<(BB * (ND + ED) + 255) / 256, 256>>>();

    // final MLP
    gemm_k<3><<<dim3((BB + 127) / 128, 4), 256>>>(hsub, nullptr, Wf1, bf1,
        h1, nullptr, nullptr, nullptr, nullptr, BB, 384, 512);
    gemm_k<4><<<dim3((BB + 127) / 128, 2), 256>>>(h1, nullptr, Wf2, bf2,
        outp, nullptr, nullptr, nullptr, nullptr, BB, 512, 256);

    if (out_size >= BB * EMBD + NN) {
        k_copy_batch<<<(NN + 255) / 256, 256>>>(outp + BB * EMBD);
    }
}

// round 9
// speedup vs baseline: 4.4606x; 4.4606x over previous
#include <cuda_runtime.h>
#include <math.h>
#include <stdint.h>

#define NN 100000
#define EE 640000
#define BB 2000
#define ND 256
#define ED 128
#define EMBD 256
#define LBLK 3

// ------------------------- scratch (no allocations allowed) -------------------------
__device__ float g_hn0[NN * ND];
__device__ float g_hn1[NN * ND];
__device__ float g_he0[EE * ED];
__device__ float g_he1[EE * ED];
__device__ float g_agg[NN * ND];
__device__ float g_U[NN * 256];       // [U_src | U_dst] per node
__device__ float g_Msrc[NN * 256];    // hn @ W_msg_top per node
__device__ float g_Wsd[256 * 256];    // packed [Ws | Wd]
__device__ float g_dist[EE];
__device__ int   g_src[EE];
__device__ int   g_dst[EE];
__device__ int   g_bn[NN];
__device__ int   g_be[EE];
__device__ int   g_is64;
__device__ float g_sum_n[BB * ND];
__device__ float g_sum_e[BB * ED];
__device__ float g_cnt_n[BB];
__device__ float g_cnt_e[BB];
__device__ float g_hsub[BB * (ND + ED)];
__device__ float g_h1[BB * 2 * EMBD];

// ------------------------- dtype detection (int32 vs int64 indices) -------------------------
__global__ void k_detect(const unsigned int* __restrict__ u) {
    if (threadIdx.x != 0 || blockIdx.x != 0) return;
    int odd_nonzero = 0;
    for (int i = 0; i < 64; i++)
        if (u[2 * i + 1] != 0u) odd_nonzero++;
    g_is64 = (odd_nonzero == 0) ? 1 : 0;
}

__global__ void k_cvt_off(const void* __restrict__ p, int n, int off,
                          int* __restrict__ outp) {
    int i = blockIdx.x * 256 + threadIdx.x;
    if (i >= n) return;
    if (g_is64) outp[i] = (int)((const long long*)p)[off + i];
    else        outp[i] = ((const int*)p)[off + i];
}

// ------------------------- prep -------------------------
__global__ void k_prep_edge(const float* __restrict__ pos) {
    int e = blockIdx.x * 256 + threadIdx.x;
    if (e >= EE) return;
    int s = g_src[e], d = g_dst[e];
    float dx = pos[d * 3 + 0] - pos[s * 3 + 0];
    float dy = pos[d * 3 + 1] - pos[s * 3 + 1];
    float dz = pos[d * 3 + 2] - pos[s * 3 + 2];
    g_dist[e] = sqrtf(dx * dx + dy * dy + dz * dz);
}

// pack W_sd[k][0:128] = W_eu[128+k][:], W_sd[k][128:256] = W_eu[384+k][:]
__global__ void k_pack_wsd(const float* __restrict__ Weu) {
    int i = blockIdx.x * 256 + threadIdx.x;
    if (i >= 256 * 256) return;
    int k = i >> 8, j = i & 255;
    float v = (j < 128) ? Weu[(128 + k) * 128 + j] : Weu[(384 + k) * 128 + (j - 128)];
    g_Wsd[i] = v;
}

// ------------------------- embeddings -------------------------
__global__ void k_embed_node(const float* __restrict__ hfeat,
                             const float* __restrict__ W,
                             float* __restrict__ outp) {
    __shared__ float sw[16 * 256];
    for (int i = threadIdx.x; i < 16 * 256; i += 256) sw[i] = W[i];
    __syncthreads();
    int c = threadIdx.x;
    int n0 = blockIdx.x * 8;
    for (int r = 0; r < 8; r++) {
        int n = n0 + r;
        if (n >= NN) return;
        float acc = 0.f;
#pragma unroll
        for (int k = 0; k < 16; k++) acc += hfeat[n * 16 + k] * sw[k * 256 + c];
        outp[(size_t)n * 256 + c] = acc;
    }
}

__global__ void k_embed_edge(const float* __restrict__ hfeat,
                             const float* __restrict__ W,
                             float* __restrict__ outp) {
    __shared__ float sw[5 * 128];
    for (int i = threadIdx.x; i < 5 * 128; i += 256) sw[i] = W[i];
    __syncthreads();
    int sub = threadIdx.x >> 7;
    int c   = threadIdx.x & 127;
    int e0  = blockIdx.x * 16 + sub;
    for (int r = 0; r < 16; r += 2) {
        int e = e0 + r;
        if (e >= EE) return;
        float acc = 0.f;
#pragma unroll
        for (int k = 0; k < 5; k++) acc += hfeat[e * 5 + k] * sw[k * 128 + c];
        outp[(size_t)e * 128 + c] = acc;
    }
}

// ------------------------- zero -------------------------
__global__ void k_zero(float* __restrict__ p, int n) {
    int i = blockIdx.x * blockDim.x + threadIdx.x;
    int str = gridDim.x * blockDim.x;
    for (; i < n; i += str) p[i] = 0.f;
}

// ------------------------- tiled SGEMM, all-contiguous A, mode-specific epilogue ----
// MODE 0 (edge):  A=he[E,128] K=128 N=128; epi: relu(acc+b+U[src][c]+U[dst][128+c]+dist*wdist[c])
// MODE 1 (msg):   A=he_new[E,128] K=128 N=256; epi: relu(acc+b+Msrc[src][c]) -> red.add agg[dst]
// MODE 2 (node):  A=[hn|agg] K=512 N=256; epi: hn + relu(acc+b)
// MODE 3 (mlp1):  A generic; relu(acc+b)
// MODE 4 (mlp2):  A generic; acc+b
// MODE 5 (plain): A generic; acc (no bias)
template <int MODE>
__global__ __launch_bounds__(256) void gemm_k(
    const float* __restrict__ P0, const float* __restrict__ P1,
    const float* __restrict__ Wb, const float* __restrict__ bias,
    float* __restrict__ Cout, const float* __restrict__ Extra,
    const int* __restrict__ src, const int* __restrict__ dst,
    const float* __restrict__ distv, const float* __restrict__ G,
    const float* __restrict__ wdist,
    int Mrows, int Kdim, int Ncols)
{
    __shared__ __align__(16) float As[16][128];
    __shared__ __align__(16) float Bs[16][128];
    const int tid = threadIdx.x;
    const int tx = tid & 15, ty = tid >> 4;
    const int m0 = blockIdx.x * 128;
    const int n0 = blockIdx.y * 128;

    float acc[8][8];
#pragma unroll
    for (int i = 0; i < 8; i++)
#pragma unroll
        for (int j = 0; j < 8; j++) acc[i][j] = 0.f;

    const int ar  = tid & 127;
    const int ak0 = (tid >> 7) * 8;
    const int rowg = m0 + ar;
    const bool rvalid = (rowg < Mrows);

    const int KT = Kdim >> 4;            // all K are multiples of 16
    for (int kt = 0; kt < KT; kt++) {
        // ---- A tile: contiguous 8-float run per thread, float4 x2 ----
        {
            const int k0 = kt * 16 + ak0;
            float4 v0 = make_float4(0.f, 0.f, 0.f, 0.f);
            float4 v1 = v0;
            if (rvalid) {
                const float* ap;
                if (MODE == 0 || MODE == 1)      ap = P0 + (size_t)rowg * 128 + k0;
                else if (MODE == 2)              ap = (k0 < 256) ? P0 + (size_t)rowg * 256 + k0
                                                                : P1 + (size_t)rowg * 256 + (k0 - 256);
                else                             ap = P0 + (size_t)rowg * Kdim + k0;
                v0 = *(const float4*)ap;
                v1 = *(const float4*)(ap + 4);
            }
            As[ak0 + 0][ar] = v0.x; As[ak0 + 1][ar] = v0.y;
            As[ak0 + 2][ar] = v0.z; As[ak0 + 3][ar] = v0.w;
            As[ak0 + 4][ar] = v1.x; As[ak0 + 5][ar] = v1.y;
            As[ak0 + 6][ar] = v1.z; As[ak0 + 7][ar] = v1.w;
        }
        // ---- B tile (weights [K, Ncols] row-major, coalesced float4) ----
#pragma unroll
        for (int r = 0; r < 2; r++) {
            int f  = tid + r * 256;
            int bk = f >> 5;
            int bc = (f & 31) * 4;
            int kg = kt * 16 + bk;
            *(float4*)&Bs[bk][bc] = *(const float4*)(Wb + (size_t)kg * Ncols + n0 + bc);
        }
        __syncthreads();
#pragma unroll
        for (int kk = 0; kk < 16; kk++) {
            float a[8], b[8];
            *(float4*)&a[0] = *(const float4*)&As[kk][ty * 8];
            *(float4*)&a[4] = *(const float4*)&As[kk][ty * 8 + 4];
            *(float4*)&b[0] = *(const float4*)&Bs[kk][tx * 8];
            *(float4*)&b[4] = *(const float4*)&Bs[kk][tx * 8 + 4];
#pragma unroll
            for (int i = 0; i < 8; i++)
#pragma unroll
                for (int j = 0; j < 8; j++) acc[i][j] += a[i] * b[j];
        }
        __syncthreads();
    }

    // ---- epilogue ----
    const int cg0 = n0 + tx * 8;
    float bia[8], wd[8];
    if (MODE != 5) {
        *(float4*)&bia[0] = *(const float4*)(bias + cg0);
        *(float4*)&bia[4] = *(const float4*)(bias + cg0 + 4);
    }
    if (MODE == 0) {
        *(float4*)&wd[0] = *(const float4*)(wdist + cg0);
        *(float4*)&wd[4] = *(const float4*)(wdist + cg0 + 4);
    }

#pragma unroll
    for (int i = 0; i < 8; i++) {
        int rg = m0 + ty * 8 + i;
        if (rg >= Mrows) continue;
        float vals[8];
        if (MODE == 0) {
            int sg = src[rg], dg = dst[rg];
            float dv = distv[rg];
            float gs[8], gd[8];
            *(float4*)&gs[0] = *(const float4*)(G + (size_t)sg * 256 + cg0);
            *(float4*)&gs[4] = *(const float4*)(G + (size_t)sg * 256 + cg0 + 4);
            *(float4*)&gd[0] = *(const float4*)(G + (size_t)dg * 256 + 128 + cg0);
            *(float4*)&gd[4] = *(const float4*)(G + (size_t)dg * 256 + 128 + cg0 + 4);
#pragma unroll
            for (int j = 0; j < 8; j++)
                vals[j] = fmaxf(acc[i][j] + bia[j] + gs[j] + gd[j] + dv * wd[j], 0.f);
            *(float4*)(Cout + (size_t)rg * 128 + cg0)     = *(float4*)&vals[0];
            *(float4*)(Cout + (size_t)rg * 128 + cg0 + 4) = *(float4*)&vals[4];
        } else if (MODE == 1) {
            int sg = src[rg], dg = dst[rg];
            float gs[8];
            *(float4*)&gs[0] = *(const float4*)(G + (size_t)sg * 256 + cg0);
            *(float4*)&gs[4] = *(const float4*)(G + (size_t)sg * 256 + cg0 + 4);
#pragma unroll
            for (int j = 0; j < 8; j++)
                vals[j] = fmaxf(acc[i][j] + bia[j] + gs[j], 0.f);
            float* ap = Cout + (size_t)dg * 256 + cg0;
            asm volatile("red.global.add.v4.f32 [%0], {%1,%2,%3,%4};"
                         :: "l"(ap), "f"(vals[0]), "f"(vals[1]), "f"(vals[2]), "f"(vals[3])
                         : "memory");
            asm volatile("red.global.add.v4.f32 [%0], {%1,%2,%3,%4};"
                         :: "l"(ap + 4), "f"(vals[4]), "f"(vals[5]), "f"(vals[6]), "f"(vals[7])
                         : "memory");
        } else if (MODE == 2) {
            float ex[8];
            *(float4*)&ex[0] = *(const float4*)(Extra + (size_t)rg * 256 + cg0);
            *(float4*)&ex[4] = *(const float4*)(Extra + (size_t)rg * 256 + cg0 + 4);
#pragma unroll
            for (int j = 0; j < 8; j++)
                vals[j] = ex[j] + fmaxf(acc[i][j] + bia[j], 0.f);
            *(float4*)(Cout + (size_t)rg * 256 + cg0)     = *(float4*)&vals[0];
            *(float4*)(Cout + (size_t)rg * 256 + cg0 + 4) = *(float4*)&vals[4];
        } else {
#pragma unroll
            for (int j = 0; j < 8; j++) {
                float v = acc[i][j] + (MODE == 5 ? 0.f : bia[j]);
                if (MODE == 3) v = fmaxf(v, 0.f);
                vals[j] = v;
            }
            *(float4*)(Cout + (size_t)rg * Ncols + cg0)     = *(float4*)&vals[0];
            *(float4*)(Cout + (size_t)rg * Ncols + cg0 + 4) = *(float4*)&vals[4];
        }
    }
}

// ------------------------- pooling -------------------------
__global__ void k_count(const int* __restrict__ b, int n, float* __restrict__ cnt) {
    int i = blockIdx.x * 256 + threadIdx.x;
    if (i < n) atomicAdd(&cnt[b[i]], 1.f);
}

__global__ void k_pool_node(const float* __restrict__ hn) {
    int n0 = blockIdx.x * 128;
    int c = threadIdx.x;
    float acc = 0.f;
    int cur = -1;
    for (int i = 0; i < 128; i++) {
        int n = n0 + i;
        if (n >= NN) break;
        int b = g_bn[n];
        if (b != cur) {
            if (cur >= 0) atomicAdd(&g_sum_n[cur * ND + c], acc);
            cur = b; acc = 0.f;
        }
        acc += hn[(size_t)n * ND + c];
    }
    if (cur >= 0) atomicAdd(&g_sum_n[cur * ND + c], acc);
}

__global__ void k_pool_edge(const float* __restrict__ he) {
    int e0 = blockIdx.x * 512;
    int c = threadIdx.x;
    float acc = 0.f;
    int cur = -1;
    for (int i = 0; i < 512; i++) {
        int e = e0 + i;
        if (e >= EE) break;
        int b = g_be[e];
        if (b != cur) {
            if (cur >= 0) atomicAdd(&g_sum_e[cur * ED + c], acc);
            cur = b; acc = 0.f;
        }
        acc += he[(size_t)e * ED + c];
    }
    if (cur >= 0) atomicAdd(&g_sum_e[cur * ED + c], acc);
}

__global__ void k_hsub() {
    int idx = blockIdx.x * 256 + threadIdx.x;
    if (idx >= BB * (ND + ED)) return;
    int b = idx / (ND + ED);
    int c = idx % (ND + ED);
    float v;
    if (c < ND) v = g_sum_n[b * ND + c] / fmaxf(g_cnt_n[b], 1.f);
    else        v = g_sum_e[b * ED + (c - ND)] / fmaxf(g_cnt_e[b], 1.f);
    g_hsub[idx] = v;
}

__global__ void k_copy_batch(float* __restrict__ outp) {
    int i = blockIdx.x * 256 + threadIdx.x;
    if (i < NN) outp[i] = (float)g_bn[i];
}

// ------------------------- launch -------------------------
extern "C" void kernel_launch(void* const* d_in, const int* in_sizes, int n_in,
                              void* d_out, int out_size) {
    const float* h_node = (const float*)d_in[0];
    const float* pos    = (const float*)d_in[1];
    const float* h_edge = (const float*)d_in[2];
    const float* W_node = (const float*)d_in[3];
    const float* W_edge = (const float*)d_in[4];
    const float* W_eu   = (const float*)d_in[5];
    const float* b_eu   = (const float*)d_in[6];
    const float* W_msg  = (const float*)d_in[7];
    const float* b_msg  = (const float*)d_in[8];
    const float* W_nu   = (const float*)d_in[9];
    const float* b_nu   = (const float*)d_in[10];
    const float* Wf1    = (const float*)d_in[11];
    const float* bf1    = (const float*)d_in[12];
    const float* Wf2    = (const float*)d_in[13];
    const float* bf2    = (const float*)d_in[14];
    const void*  ei     = d_in[15];
    const void*  bn     = d_in[16];
    const void*  be     = d_in[17];
    float* outp = (float*)d_out;

    float *hn0, *hn1, *he0, *he1, *agg, *Up, *Mp, *Wsd, *distp;
    float *sumn, *sume, *cntn, *cnte, *hsub, *h1;
    int *srcp, *dstp, *bnp, *bep;
    cudaGetSymbolAddress((void**)&hn0, g_hn0);
    cudaGetSymbolAddress((void**)&hn1, g_hn1);
    cudaGetSymbolAddress((void**)&he0, g_he0);
    cudaGetSymbolAddress((void**)&he1, g_he1);
    cudaGetSymbolAddress((void**)&agg, g_agg);
    cudaGetSymbolAddress((void**)&Up,  g_U);
    cudaGetSymbolAddress((void**)&Mp,  g_Msrc);
    cudaGetSymbolAddress((void**)&Wsd, g_Wsd);
    cudaGetSymbolAddress((void**)&distp, g_dist);
    cudaGetSymbolAddress((void**)&srcp, g_src);
    cudaGetSymbolAddress((void**)&dstp, g_dst);
    cudaGetSymbolAddress((void**)&bnp, g_bn);
    cudaGetSymbolAddress((void**)&bep, g_be);
    cudaGetSymbolAddress((void**)&sumn, g_sum_n);
    cudaGetSymbolAddress((void**)&sume, g_sum_e);
    cudaGetSymbolAddress((void**)&cntn, g_cnt_n);
    cudaGetSymbolAddress((void**)&cnte, g_cnt_e);
    cudaGetSymbolAddress((void**)&hsub, g_hsub);
    cudaGetSymbolAddress((void**)&h1, g_h1);

    // normalize index dtypes
    k_detect<<<1, 32>>>((const unsigned int*)ei);
    k_cvt_off<<<(EE + 255) / 256, 256>>>(ei, EE, 0,  srcp);
    k_cvt_off<<<(EE + 255) / 256, 256>>>(ei, EE, EE, dstp);
    k_cvt_off<<<(NN + 255) / 256, 256>>>(bn, NN, 0,  bnp);
    k_cvt_off<<<(EE + 255) / 256, 256>>>(be, EE, 0,  bep);

    k_prep_edge<<<(EE + 255) / 256, 256>>>(pos);
    k_embed_node<<<(NN + 7) / 8, 256>>>(h_node, W_node, hn0);
    k_embed_edge<<<EE / 16, 256>>>(h_edge, W_edge, he0);

    float *hnc = hn0, *hnn = hn1, *hec = he0, *hen = he1;
    for (int l = 0; l < LBLK; l++) {
        const float* Weu_l  = W_eu  + (size_t)l * 641 * 128;
        const float* Wmsg_l = W_msg + (size_t)l * 384 * 256;
        const float* Wnu_l  = W_nu  + (size_t)l * 512 * 256;

        // node-side precomputes
        k_pack_wsd<<<256, 256>>>(Weu_l);
        gemm_k<5><<<dim3((NN + 127) / 128, 2), 256>>>(hnc, nullptr, Wsd, nullptr,
            Up, nullptr, nullptr, nullptr, nullptr, nullptr, nullptr, NN, 256, 256);
        gemm_k<5><<<dim3((NN + 127) / 128, 2), 256>>>(hnc, nullptr, Wmsg_l, nullptr,
            Mp, nullptr, nullptr, nullptr, nullptr, nullptr, nullptr, NN, 256, 256);
        k_zero<<<4096, 256>>>(agg, NN * ND);

        // edge update: he_new = relu(he@W_he + U[src|dst] + dist*wdist + b)
        gemm_k<0><<<dim3(EE / 128, 1), 256>>>(hec, nullptr, Weu_l, b_eu + l * 128,
            hen, nullptr, srcp, dstp, distp, Up, Weu_l + 640 * 128, EE, 128, 128);

        // messages: relu(he_new@W_bot + Msrc[src] + b) scatter-> agg[dst]
        gemm_k<1><<<dim3(EE / 128, 2), 256>>>(hen, nullptr, Wmsg_l + 256 * 256,
            b_msg + l * 256, agg, nullptr, srcp, dstp, nullptr, Mp, nullptr, EE, 128, 256);

        // node update: hn = hn + relu([hn|agg]@W_nu + b)
        gemm_k<2><<<dim3((NN + 127) / 128, 2), 256>>>(hnc, agg, Wnu_l, b_nu + l * 256,
            hnn, hnc, nullptr, nullptr, nullptr, nullptr, nullptr, NN, 512, 256);

        { float* tp = hnc; hnc = hnn; hnn = tp; }
        { float* tp = hec; hec = hen; hen = tp; }
    }

    // pooling
    k_zero<<<256, 256>>>(sumn, BB * ND);
    k_zero<<<256, 256>>>(sume, BB * ED);
    k_zero<<<8, 256>>>(cntn, BB);
    k_zero<<<8, 256>>>(cnte, BB);
    k_count<<<(NN + 255) / 256, 256>>>(bnp, NN, cntn);
    k_count<<<(EE + 255) / 256, 256>>>(bep, EE, cnte);
    k_pool_node<<<(NN + 127) / 128, 256>>>(hnc);
    k_pool_edge<<<(EE + 511) / 512, 128>>>(hec);
    k_hsub<<<(BB * (ND + ED) + 255) / 256, 256>>>();

    // final MLP
    gemm_k<3><<<dim3((BB + 127) / 128, 4), 256>>>(hsub, nullptr, Wf1, bf1,
        h1, nullptr, nullptr, nullptr, nullptr, nullptr, nullptr, BB, 384, 512);
    gemm_k<4><<<dim3((BB + 127) / 128, 2), 256>>>(h1, nullptr, Wf2, bf2,
        outp, nullptr, nullptr, nullptr, nullptr, nullptr, nullptr, BB, 512, 256);

    if (out_size >= BB * EMBD + NN) {
        k_copy_batch<<<(NN + 255) / 256, 256>>>(outp + BB * EMBD);
    }
}

// round 10
// speedup vs baseline: 4.8209x; 1.0808x over previous
#include <cuda_runtime.h>
#include <math.h>
#include <stdint.h>

#define NN 100000
#define EE 640000
#define BB 2000
#define ND 256
#define ED 128
#define EMBD 256
#define LBLK 3

// ------------------------- scratch (no allocations allowed) -------------------------
__device__ float g_hn0[NN * ND];
__device__ float g_hn1[NN * ND];
__device__ float g_he0[EE * ED];
__device__ float g_he1[EE * ED];
__device__ float g_agg[NN * ND];
__device__ float g_U[NN * 256];       // [U_src | U_dst] per node
__device__ float g_Msrc[NN * 256];    // hn @ W_msg_top per node
__device__ float g_Wsd[256 * 256];    // packed [Ws | Wd]
__device__ float g_dist[EE];
__device__ int   g_src[EE];
__device__ int   g_dst[EE];
__device__ int   g_bn[NN];
__device__ int   g_be[EE];
__device__ int   g_is64;
__device__ float g_sum_n[BB * ND];
__device__ float g_sum_e[BB * ED];
__device__ float g_cnt_n[BB];
__device__ float g_cnt_e[BB];
__device__ float g_hsub[BB * (ND + ED)];
__device__ float g_h1[BB * 2 * EMBD];

// ------------------------- f32x2 helpers -------------------------
__device__ __forceinline__ unsigned long long pack_dup(float a) {
    unsigned long long r;
    asm("mov.b64 %0, {%1, %1};" : "=l"(r) : "f"(a));
    return r;
}
__device__ __forceinline__ unsigned long long pack2(float lo, float hi) {
    unsigned long long r;
    asm("mov.b64 %0, {%1, %2};" : "=l"(r) : "f"(lo), "f"(hi));
    return r;
}
__device__ __forceinline__ void unpack2(unsigned long long v, float& lo, float& hi) {
    asm("mov.b64 {%0, %1}, %2;" : "=f"(lo), "=f"(hi) : "l"(v));
}
#define FMA2(acc, a, b) \
    asm("fma.rn.f32x2 %0, %1, %2, %0;" : "+l"(acc) : "l"(a), "l"(b))

// ------------------------- dtype detection (int32 vs int64 indices) -------------------------
__global__ void k_detect(const unsigned int* __restrict__ u) {
    if (threadIdx.x != 0 || blockIdx.x != 0) return;
    int odd_nonzero = 0;
    for (int i = 0; i < 64; i++)
        if (u[2 * i + 1] != 0u) odd_nonzero++;
    g_is64 = (odd_nonzero == 0) ? 1 : 0;
}

__global__ void k_cvt_off(const void* __restrict__ p, int n, int off,
                          int* __restrict__ outp) {
    int i = blockIdx.x * 256 + threadIdx.x;
    if (i >= n) return;
    if (g_is64) outp[i] = (int)((const long long*)p)[off + i];
    else        outp[i] = ((const int*)p)[off + i];
}

// ------------------------- prep -------------------------
__global__ void k_prep_edge(const float* __restrict__ pos) {
    int e = blockIdx.x * 256 + threadIdx.x;
    if (e >= EE) return;
    int s = g_src[e], d = g_dst[e];
    float dx = pos[d * 3 + 0] - pos[s * 3 + 0];
    float dy = pos[d * 3 + 1] - pos[s * 3 + 1];
    float dz = pos[d * 3 + 2] - pos[s * 3 + 2];
    g_dist[e] = sqrtf(dx * dx + dy * dy + dz * dz);
}

// pack W_sd[k][0:128] = W_eu[128+k][:], W_sd[k][128:256] = W_eu[384+k][:]
__global__ void k_pack_wsd(const float* __restrict__ Weu) {
    int i = blockIdx.x * 256 + threadIdx.x;
    if (i >= 256 * 256) return;
    int k = i >> 8, j = i & 255;
    float v = (j < 128) ? Weu[(128 + k) * 128 + j] : Weu[(384 + k) * 128 + (j - 128)];
    g_Wsd[i] = v;
}

// ------------------------- embeddings -------------------------
__global__ void k_embed_node(const float* __restrict__ hfeat,
                             const float* __restrict__ W,
                             float* __restrict__ outp) {
    __shared__ float sw[16 * 256];
    for (int i = threadIdx.x; i < 16 * 256; i += 256) sw[i] = W[i];
    __syncthreads();
    int c = threadIdx.x;
    int n0 = blockIdx.x * 8;
    for (int r = 0; r < 8; r++) {
        int n = n0 + r;
        if (n >= NN) return;
        float acc = 0.f;
#pragma unroll
        for (int k = 0; k < 16; k++) acc += hfeat[n * 16 + k] * sw[k * 256 + c];
        outp[(size_t)n * 256 + c] = acc;
    }
}

__global__ void k_embed_edge(const float* __restrict__ hfeat,
                             const float* __restrict__ W,
                             float* __restrict__ outp) {
    __shared__ float sw[5 * 128];
    for (int i = threadIdx.x; i < 5 * 128; i += 256) sw[i] = W[i];
    __syncthreads();
    int sub = threadIdx.x >> 7;
    int c   = threadIdx.x & 127;
    int e0  = blockIdx.x * 16 + sub;
    for (int r = 0; r < 16; r += 2) {
        int e = e0 + r;
        if (e >= EE) return;
        float acc = 0.f;
#pragma unroll
        for (int k = 0; k < 5; k++) acc += hfeat[e * 5 + k] * sw[k * 128 + c];
        outp[(size_t)e * 128 + c] = acc;
    }
}

// ------------------------- zero -------------------------
__global__ void k_zero(float* __restrict__ p, int n) {
    int i = blockIdx.x * blockDim.x + threadIdx.x;
    int str = gridDim.x * blockDim.x;
    for (; i < n; i += str) p[i] = 0.f;
}

// ------------------------- tiled SGEMM (FFMA2 inner), mode-specific epilogue ----
// MODE 0 (edge):  A=he[E,128] K=128 N=128; epi: relu(acc+b+U[src][c]+U[dst][128+c]+dist*wdist[c])
// MODE 1 (msg):   A=he_new[E,128] K=128 N=256; epi: relu(acc+b+Msrc[src][c]) -> red.add agg[dst]
// MODE 2 (node):  A=[hn|agg] K=512 N=256; epi: hn + relu(acc+b)
// MODE 3 (mlp1):  A generic; relu(acc+b)
// MODE 4 (mlp2):  A generic; acc+b
// MODE 5 (plain): A generic; acc (no bias)
template <int MODE>
__global__ __launch_bounds__(256) void gemm_k(
    const float* __restrict__ P0, const float* __restrict__ P1,
    const float* __restrict__ Wb, const float* __restrict__ bias,
    float* __restrict__ Cout, const float* __restrict__ Extra,
    const int* __restrict__ src, const int* __restrict__ dst,
    const float* __restrict__ distv, const float* __restrict__ G,
    const float* __restrict__ wdist,
    int Mrows, int Kdim, int Ncols)
{
    __shared__ __align__(16) float As[16][128];
    __shared__ __align__(16) float Bs[16][128];
    const int tid = threadIdx.x;
    const int tx = tid & 15, ty = tid >> 4;
    const int m0 = blockIdx.x * 128;
    const int n0 = blockIdx.y * 128;

    // packed accumulators: acc2[i][jq] holds columns (2*jq, 2*jq+1) for row i
    unsigned long long acc2[8][4];
#pragma unroll
    for (int i = 0; i < 8; i++)
#pragma unroll
        for (int j = 0; j < 4; j++) acc2[i][j] = 0ull;

    const int ar  = tid & 127;
    const int ak0 = (tid >> 7) * 8;
    const int rowg = m0 + ar;
    const bool rvalid = (rowg < Mrows);

    const int KT = Kdim >> 4;            // all K are multiples of 16
    for (int kt = 0; kt < KT; kt++) {
        // ---- A tile: contiguous 8-float run per thread, float4 x2 ----
        {
            const int k0 = kt * 16 + ak0;
            float4 v0 = make_float4(0.f, 0.f, 0.f, 0.f);
            float4 v1 = v0;
            if (rvalid) {
                const float* ap;
                if (MODE == 0 || MODE == 1)      ap = P0 + (size_t)rowg * 128 + k0;
                else if (MODE == 2)              ap = (k0 < 256) ? P0 + (size_t)rowg * 256 + k0
                                                                : P1 + (size_t)rowg * 256 + (k0 - 256);
                else                             ap = P0 + (size_t)rowg * Kdim + k0;
                v0 = *(const float4*)ap;
                v1 = *(const float4*)(ap + 4);
            }
            As[ak0 + 0][ar] = v0.x; As[ak0 + 1][ar] = v0.y;
            As[ak0 + 2][ar] = v0.z; As[ak0 + 3][ar] = v0.w;
            As[ak0 + 4][ar] = v1.x; As[ak0 + 5][ar] = v1.y;
            As[ak0 + 6][ar] = v1.z; As[ak0 + 7][ar] = v1.w;
        }
        // ---- B tile (weights [K, Ncols] row-major, coalesced float4) ----
#pragma unroll
        for (int r = 0; r < 2; r++) {
            int f  = tid + r * 256;
            int bk = f >> 5;
            int bc = (f & 31) * 4;
            int kg = kt * 16 + bk;
            *(float4*)&Bs[bk][bc] = *(const float4*)(Wb + (size_t)kg * Ncols + n0 + bc);
        }
        __syncthreads();
#pragma unroll
        for (int kk = 0; kk < 16; kk++) {
            float a[8], b[8];
            *(float4*)&a[0] = *(const float4*)&As[kk][ty * 8];
            *(float4*)&a[4] = *(const float4*)&As[kk][ty * 8 + 4];
            *(float4*)&b[0] = *(const float4*)&Bs[kk][tx * 8];
            *(float4*)&b[4] = *(const float4*)&Bs[kk][tx * 8 + 4];
            unsigned long long b2[4];
#pragma unroll
            for (int j = 0; j < 4; j++) b2[j] = pack2(b[2 * j], b[2 * j + 1]);
#pragma unroll
            for (int i = 0; i < 8; i++) {
                unsigned long long pa = pack_dup(a[i]);
#pragma unroll
                for (int j = 0; j < 4; j++) FMA2(acc2[i][j], pa, b2[j]);
            }
        }
        __syncthreads();
    }

    // ---- epilogue ----
    const int cg0 = n0 + tx * 8;
    float bia[8], wd[8];
    if (MODE != 5) {
        *(float4*)&bia[0] = *(const float4*)(bias + cg0);
        *(float4*)&bia[4] = *(const float4*)(bias + cg0 + 4);
    }
    if (MODE == 0) {
        *(float4*)&wd[0] = *(const float4*)(wdist + cg0);
        *(float4*)&wd[4] = *(const float4*)(wdist + cg0 + 4);
    }

#pragma unroll
    for (int i = 0; i < 8; i++) {
        int rg = m0 + ty * 8 + i;
        if (rg >= Mrows) continue;
        float accr[8];
#pragma unroll
        for (int j = 0; j < 4; j++) unpack2(acc2[i][j], accr[2 * j], accr[2 * j + 1]);
        float vals[8];
        if (MODE == 0) {
            int sg = src[rg], dg = dst[rg];
            float dv = distv[rg];
            float gs[8], gd[8];
            *(float4*)&gs[0] = *(const float4*)(G + (size_t)sg * 256 + cg0);
            *(float4*)&gs[4] = *(const float4*)(G + (size_t)sg * 256 + cg0 + 4);
            *(float4*)&gd[0] = *(const float4*)(G + (size_t)dg * 256 + 128 + cg0);
            *(float4*)&gd[4] = *(const float4*)(G + (size_t)dg * 256 + 128 + cg0 + 4);
#pragma unroll
            for (int j = 0; j < 8; j++)
                vals[j] = fmaxf(accr[j] + bia[j] + gs[j] + gd[j] + dv * wd[j], 0.f);
            *(float4*)(Cout + (size_t)rg * 128 + cg0)     = *(float4*)&vals[0];
            *(float4*)(Cout + (size_t)rg * 128 + cg0 + 4) = *(float4*)&vals[4];
        } else if (MODE == 1) {
            int sg = src[rg], dg = dst[rg];
            float gs[8];
            *(float4*)&gs[0] = *(const float4*)(G + (size_t)sg * 256 + cg0);
            *(float4*)&gs[4] = *(const float4*)(G + (size_t)sg * 256 + cg0 + 4);
#pragma unroll
            for (int j = 0; j < 8; j++)
                vals[j] = fmaxf(accr[j] + bia[j] + gs[j], 0.f);
            float* ap = Cout + (size_t)dg * 256 + cg0;
            asm volatile("red.global.add.v4.f32 [%0], {%1,%2,%3,%4};"
                         :: "l"(ap), "f"(vals[0]), "f"(vals[1]), "f"(vals[2]), "f"(vals[3])
                         : "memory");
            asm volatile("red.global.add.v4.f32 [%0], {%1,%2,%3,%4};"
                         :: "l"(ap + 4), "f"(vals[4]), "f"(vals[5]), "f"(vals[6]), "f"(vals[7])
                         : "memory");
        } else if (MODE == 2) {
            float ex[8];
            *(float4*)&ex[0] = *(const float4*)(Extra + (size_t)rg * 256 + cg0);
            *(float4*)&ex[4] = *(const float4*)(Extra + (size_t)rg * 256 + cg0 + 4);
#pragma unroll
            for (int j = 0; j < 8; j++)
                vals[j] = ex[j] + fmaxf(accr[j] + bia[j], 0.f);
            *(float4*)(Cout + (size_t)rg * 256 + cg0)     = *(float4*)&vals[0];
            *(float4*)(Cout + (size_t)rg * 256 + cg0 + 4) = *(float4*)&vals[4];
        } else {
#pragma unroll
            for (int j = 0; j < 8; j++) {
                float v = accr[j] + (MODE == 5 ? 0.f : bia[j]);
                if (MODE == 3) v = fmaxf(v, 0.f);
                vals[j] = v;
            }
            *(float4*)(Cout + (size_t)rg * Ncols + cg0)     = *(float4*)&vals[0];
            *(float4*)(Cout + (size_t)rg * Ncols + cg0 + 4) = *(float4*)&vals[4];
        }
    }
}

// ------------------------- pooling -------------------------
__global__ void k_count(const int* __restrict__ b, int n, float* __restrict__ cnt) {
    int i = blockIdx.x * 256 + threadIdx.x;
    if (i < n) atomicAdd(&cnt[b[i]], 1.f);
}

__global__ void k_pool_node(const float* __restrict__ hn) {
    int n0 = blockIdx.x * 128;
    int c = threadIdx.x;
    float acc = 0.f;
    int cur = -1;
    for (int i = 0; i < 128; i++) {
        int n = n0 + i;
        if (n >= NN) break;
        int b = g_bn[n];
        if (b != cur) {
            if (cur >= 0) atomicAdd(&g_sum_n[cur * ND + c], acc);
            cur = b; acc = 0.f;
        }
        acc += hn[(size_t)n * ND + c];
    }
    if (cur >= 0) atomicAdd(&g_sum_n[cur * ND + c], acc);
}

__global__ void k_pool_edge(const float* __restrict__ he) {
    int e0 = blockIdx.x * 512;
    int c = threadIdx.x;
    float acc = 0.f;
    int cur = -1;
    for (int i = 0; i < 512; i++) {
        int e = e0 + i;
        if (e >= EE) break;
        int b = g_be[e];
        if (b != cur) {
            if (cur >= 0) atomicAdd(&g_sum_e[cur * ED + c], acc);
            cur = b; acc = 0.f;
        }
        acc += he[(size_t)e * ED + c];
    }
    if (cur >= 0) atomicAdd(&g_sum_e[cur * ED + c], acc);
}

__global__ void k_hsub() {
    int idx = blockIdx.x * 256 + threadIdx.x;
    if (idx >= BB * (ND + ED)) return;
    int b = idx / (ND + ED);
    int c = idx % (ND + ED);
    float v;
    if (c < ND) v = g_sum_n[b * ND + c] / fmaxf(g_cnt_n[b], 1.f);
    else        v = g_sum_e[b * ED + (c - ND)] / fmaxf(g_cnt_e[b], 1.f);
    g_hsub[idx] = v;
}

__global__ void k_copy_batch(float* __restrict__ outp) {
    int i = blockIdx.x * 256 + threadIdx.x;
    if (i < NN) outp[i] = (float)g_bn[i];
}

// ------------------------- launch -------------------------
extern "C" void kernel_launch(void* const* d_in, const int* in_sizes, int n_in,
                              void* d_out, int out_size) {
    const float* h_node = (const float*)d_in[0];
    const float* pos    = (const float*)d_in[1];
    const float* h_edge = (const float*)d_in[2];
    const float* W_node = (const float*)d_in[3];
    const float* W_edge = (const float*)d_in[4];
    const float* W_eu   = (const float*)d_in[5];
    const float* b_eu   = (const float*)d_in[6];
    const float* W_msg  = (const float*)d_in[7];
    const float* b_msg  = (const float*)d_in[8];
    const float* W_nu   = (const float*)d_in[9];
    const float* b_nu   = (const float*)d_in[10];
    const float* Wf1    = (const float*)d_in[11];
    const float* bf1    = (const float*)d_in[12];
    const float* Wf2    = (const float*)d_in[13];
    const float* bf2    = (const float*)d_in[14];
    const void*  ei     = d_in[15];
    const void*  bn     = d_in[16];
    const void*  be     = d_in[17];
    float* outp = (float*)d_out;

    float *hn0, *hn1, *he0, *he1, *agg, *Up, *Mp, *Wsd, *distp;
    float *sumn, *sume, *cntn, *cnte, *hsub, *h1;
    int *srcp, *dstp, *bnp, *bep;
    cudaGetSymbolAddress((void**)&hn0, g_hn0);
    cudaGetSymbolAddress((void**)&hn1, g_hn1);
    cudaGetSymbolAddress((void**)&he0, g_he0);
    cudaGetSymbolAddress((void**)&he1, g_he1);
    cudaGetSymbolAddress((void**)&agg, g_agg);
    cudaGetSymbolAddress((void**)&Up,  g_U);
    cudaGetSymbolAddress((void**)&Mp,  g_Msrc);
    cudaGetSymbolAddress((void**)&Wsd, g_Wsd);
    cudaGetSymbolAddress((void**)&distp, g_dist);
    cudaGetSymbolAddress((void**)&srcp, g_src);
    cudaGetSymbolAddress((void**)&dstp, g_dst);
    cudaGetSymbolAddress((void**)&bnp, g_bn);
    cudaGetSymbolAddress((void**)&bep, g_be);
    cudaGetSymbolAddress((void**)&sumn, g_sum_n);
    cudaGetSymbolAddress((void**)&sume, g_sum_e);
    cudaGetSymbolAddress((void**)&cntn, g_cnt_n);
    cudaGetSymbolAddress((void**)&cnte, g_cnt_e);
    cudaGetSymbolAddress((void**)&hsub, g_hsub);
    cudaGetSymbolAddress((void**)&h1, g_h1);

    // normalize index dtypes
    k_detect<<<1, 32>>>((const unsigned int*)ei);
    k_cvt_off<<<(EE + 255) / 256, 256>>>(ei, EE, 0,  srcp);
    k_cvt_off<<<(EE + 255) / 256, 256>>>(ei, EE, EE, dstp);
    k_cvt_off<<<(NN + 255) / 256, 256>>>(bn, NN, 0,  bnp);
    k_cvt_off<<<(EE + 255) / 256, 256>>>(be, EE, 0,  bep);

    k_prep_edge<<<(EE + 255) / 256, 256>>>(pos);
    k_embed_node<<<(NN + 7) / 8, 256>>>(h_node, W_node, hn0);
    k_embed_edge<<<EE / 16, 256>>>(h_edge, W_edge, he0);

    float *hnc = hn0, *hnn = hn1, *hec = he0, *hen = he1;
    for (int l = 0; l < LBLK; l++) {
        const float* Weu_l  = W_eu  + (size_t)l * 641 * 128;
        const float* Wmsg_l = W_msg + (size_t)l * 384 * 256;
        const float* Wnu_l  = W_nu  + (size_t)l * 512 * 256;

        // node-side precomputes
        k_pack_wsd<<<256, 256>>>(Weu_l);
        gemm_k<5><<<dim3((NN + 127) / 128, 2), 256>>>(hnc, nullptr, Wsd, nullptr,
            Up, nullptr, nullptr, nullptr, nullptr, nullptr, nullptr, NN, 256, 256);
        gemm_k<5><<<dim3((NN + 127) / 128, 2), 256>>>(hnc, nullptr, Wmsg_l, nullptr,
            Mp, nullptr, nullptr, nullptr, nullptr, nullptr, nullptr, NN, 256, 256);
        k_zero<<<4096, 256>>>(agg, NN * ND);

        // edge update: he_new = relu(he@W_he + U[src|dst] + dist*wdist + b)
        gemm_k<0><<<dim3(EE / 128, 1), 256>>>(hec, nullptr, Weu_l, b_eu + l * 128,
            hen, nullptr, srcp, dstp, distp, Up, Weu_l + 640 * 128, EE, 128, 128);

        // messages: relu(he_new@W_bot + Msrc[src] + b) scatter-> agg[dst]
        gemm_k<1><<<dim3(EE / 128, 2), 256>>>(hen, nullptr, Wmsg_l + 256 * 256,
            b_msg + l * 256, agg, nullptr, srcp, dstp, nullptr, Mp, nullptr, EE, 128, 256);

        // node update: hn = hn + relu([hn|agg]@W_nu + b)
        gemm_k<2><<<dim3((NN + 127) / 128, 2), 256>>>(hnc, agg, Wnu_l, b_nu + l * 256,
            hnn, hnc, nullptr, nullptr, nullptr, nullptr, nullptr, NN, 512, 256);

        { float* tp = hnc; hnc = hnn; hnn = tp; }
        { float* tp = hec; hec = hen; hen = tp; }
    }

    // pooling
    k_zero<<<256, 256>>>(sumn, BB * ND);
    k_zero<<<256, 256>>>(sume, BB * ED);
    k_zero<<<8, 256>>>(cntn, BB);
    k_zero<<<8, 256>>>(cnte, BB);
    k_count<<<(NN + 255) / 256, 256>>>(bnp, NN, cntn);
    k_count<<<(EE + 255) / 256, 256>>>(bep, EE, cnte);
    k_pool_node<<<(NN + 127) / 128, 256>>>(hnc);
    k_pool_edge<<<(EE + 511) / 512, 128>>>(hec);
    k_hsub<<<(BB * (ND + ED) + 255) / 256, 256>>>();

    // final MLP
    gemm_k<3><<<dim3((BB + 127) / 128, 4), 256>>>(hsub, nullptr, Wf1, bf1,
        h1, nullptr, nullptr, nullptr, nullptr, nullptr, nullptr, BB, 384, 512);
    gemm_k<4><<<dim3((BB + 127) / 128, 2), 256>>>(h1, nullptr, Wf2, bf2,
        outp, nullptr, nullptr, nullptr, nullptr, nullptr, nullptr, BB, 512, 256);

    if (out_size >= BB * EMBD + NN) {
        k_copy_batch<<<(NN + 255) / 256, 256>>>(outp + BB * EMBD);
    }
}